// round 16
// baseline (speedup 1.0000x reference)
#include <cuda_runtime.h>
#include <math.h>
#include <stdint.h>

#define PI_F      3.14159265358979323846f
#define TWO_PI_F  6.28318530717958647692f
#define N_NEUR    512
#define GW        (PI_F / 4.0f)
#define GRID      148
#define DEPTH     3
#define NL        30
#define TG        8                        // slabs per stolen ticket
#define SLAB_FLOATS (N_NEUR * NL)          // 15360 floats
#define SLAB_BYTES  (SLAB_FLOATS * 4)      // 61440 bytes

// Scratch (static device memory, zero-initialized; no allocations anywhere)
__device__ float g_bearing[N_NEUR];        // accumulated across blocks
__device__ float g_sum_hpc = 0.0f;
__device__ int   g_count  = 0;
__device__ int   g_ticket = 0;

__device__ __forceinline__ float period_bound(float d) {
    float m = fmodf(d + PI_F, TWO_PI_F);
    if (m < 0.0f) m += TWO_PI_F;
    return m - PI_F;
}

__device__ __forceinline__ uint32_t smem_u32(const void* p) {
    return (uint32_t)__cvta_generic_to_shared(p);
}
__device__ __forceinline__ void mbar_init(uint32_t mb, uint32_t count) {
    asm volatile("mbarrier.init.shared.b64 [%0], %1;" :: "r"(mb), "r"(count) : "memory");
}
__device__ __forceinline__ void bulk_load(uint32_t dst_smem, const void* src_gmem,
                                          uint32_t bytes, uint32_t mb) {
    asm volatile("mbarrier.arrive.expect_tx.shared.b64 _, [%0], %1;"
                 :: "r"(mb), "r"(bytes) : "memory");
    asm volatile("cp.async.bulk.shared::cluster.global.mbarrier::complete_tx::bytes "
                 "[%0], [%1], %2, [%3];"
                 :: "r"(dst_smem), "l"(src_gmem), "r"(bytes), "r"(mb) : "memory");
}
__device__ __forceinline__ void mbar_wait(uint32_t mb, uint32_t parity) {
    asm volatile(
        "{\n\t"
        ".reg .pred p;\n\t"
        "WL_%=:\n\t"
        "mbarrier.try_wait.parity.shared.b64 p, [%0], %1;\n\t"
        "@!p bra WL_%=;\n\t"
        "}"
        :: "r"(mb), "r"(parity) : "memory");
}

// ---------------------------------------------------------------------------
// Fused persistent kernel (R12 proven core, TG=8 tickets).
//  148 blocks x 512 threads, dynamic work stealing (TG=8 slabs/ticket),
//  DEPTH=3 cp.async.bulk ring gated by __syncthreads.
//  Thread n accumulates sum_p w_p * dot(conn[p,n,:], rb) and publishes it
//  directly into g_bearing[n] via one coalesced atomicAdd (overlapped with
//  other blocks' streaming). Thread 0 streams the block's share of
//  sum(r_hpc) (ticket ranges partition P). Last block only runs the small
//  ODE / convolution stage and resets globals for the next graph replay.
// ---------------------------------------------------------------------------
__global__ void __launch_bounds__(N_NEUR, 1) fused_kernel(
    const float* __restrict__ conn,      // (P, 512, 30)
    const float* __restrict__ r,
    const float* __restrict__ u,
    const float* __restrict__ v,
    const float* __restrict__ r_hpc,     // (P,)
    const float* __restrict__ r_bearing, // (30,)
    const float* __restrict__ pos_estimate,
    const float* __restrict__ angular_velocity,
    const float* __restrict__ sen2hd,
    const float* __restrict__ shared_t,
    float* __restrict__ out,
    int P)
{
    extern __shared__ float buf[];                 // DEPTH * SLAB_FLOATS
    __shared__ __align__(8) unsigned long long mbar[DEPTH];
    __shared__ int   s_pidx[DEPTH];
    __shared__ int   s_last;
    __shared__ float s_red[N_NEUR];
    __shared__ float s_rr[N_NEUR];
    __shared__ float s_cn[N_NEUR];

    const int tid = threadIdx.x;

    // rb into registers (uniform; compile-time indices)
    float rbv[NL];
    #pragma unroll
    for (int l = 0; l < NL; l++) rbv[l] = __ldg(r_bearing + l);

    // ticket state lives in thread 0's registers
    int cur = 0, rem = 0;

    if (tid == 0) {
        #pragma unroll
        for (int s = 0; s < DEPTH; s++) mbar_init(smem_u32(&mbar[s]), 1u);
        // preload up to DEPTH slabs
        for (int s = 0; s < DEPTH; s++) {
            if (rem == 0) {
                cur = atomicAdd(&g_ticket, TG);
                rem = (cur < P) ? min(TG, P - cur) : 0;
            }
            if (rem > 0) {
                s_pidx[s] = cur;
                bulk_load(smem_u32(buf + s * SLAB_FLOATS),
                          conn + (size_t)cur * SLAB_FLOATS,
                          SLAB_BYTES, smem_u32(&mbar[s]));
                cur++; rem--;
            } else {
                s_pidx[s] = -1;
            }
        }
    }
    __syncthreads();  // barriers + preload indices visible

    float acc  = 0.0f;
    float wsum = 0.0f;                    // thread 0 only: block's sum(r_hpc)
    for (int it = 0; ; it++) {
        const int s = it % DEPTH;
        const int p = s_pidx[s];          // written >= DEPTH-1 barriers ago
        if (p < 0) break;

        const float w = __ldg(r_hpc + p); // broadcast load, issues early
        if (tid == 0) wsum += w;          // p's are disjoint across blocks
        mbar_wait(smem_u32(&mbar[s]), (uint32_t)((it / DEPTH) & 1));

        const float2* row = (const float2*)(buf + s * SLAB_FLOATS) + tid * (NL / 2);
        float dot = 0.0f;
        #pragma unroll
        for (int l = 0; l < NL / 2; l++) {
            float2 v2 = row[l];
            dot = fmaf(v2.x, rbv[2 * l],     dot);
            dot = fmaf(v2.y, rbv[2 * l + 1], dot);
        }
        acc = fmaf(w, dot, acc);

        __syncthreads();                  // everyone done with buf[s]
        if (tid == 0) {
            if (rem == 0) {
                cur = atomicAdd(&g_ticket, TG);
                rem = (cur < P) ? min(TG, P - cur) : 0;
            }
            if (rem > 0) {
                s_pidx[s] = cur;
                bulk_load(smem_u32(buf + s * SLAB_FLOATS),
                          conn + (size_t)cur * SLAB_FLOATS,
                          SLAB_BYTES, smem_u32(&mbar[s]));
                cur++; rem--;
            } else {
                s_pidx[s] = -1;
            }
        }
    }

    // publish: coalesced float atomics, overlapped with others' streaming
    atomicAdd(&g_bearing[tid], acc);
    if (tid == 0) atomicAdd(&g_sum_hpc, wsum);
    __threadfence();
    __syncthreads();
    if (tid == 0) {
        int old = atomicAdd(&g_count, 1);
        s_last = (old == GRID - 1);
    }
    __syncthreads();
    if (!s_last) return;

    // ------------------- last block: small final stage -------------------
    __threadfence();  // acquire all blocks' contributions

    const int n = tid;

    const float bear    = g_bearing[n];   // all adds ordered before counter
    const float sum_hpc = g_sum_hpc;
    g_bearing[n] = 0.0f;                  // reset for next graph replay
                                          // (only this block is alive now)

    const float DX   = TWO_PI_F / 512.0f;
    const float J0   = 20.0f / 512.0f;
    const float KPAR = 0.8f / 512.0f * 20.0f;

    const float xn = -PI_F + n * DX;
    const float rn = r[n];
    s_rr[n] = rn;
    {
        float dj = period_bound(n * DX);
        float q  = dj / GW;
        s_cn[n] = J0 * expf(-0.5f * q * q) / (TWO_PI_F * GW * GW);
    }

    // bump center: angle(sum exp(i x) r)
    s_red[n] = cosf(xn) * rn;
    __syncthreads();
    #pragma unroll
    for (int off = 256; off > 0; off >>= 1) {
        if (n < off) s_red[n] += s_red[n + off];
        __syncthreads();
    }
    const float csum = s_red[0];
    __syncthreads();
    s_red[n] = sinf(xn) * rn;
    __syncthreads();
    #pragma unroll
    for (int off = 256; off > 0; off >>= 1) {
        if (n < off) s_red[n] += s_red[n + off];
        __syncthreads();
    }
    const float ssum = s_red[0];
    __syncthreads();
    const float center = atan2f(ssum, csum);

    // path integration (DT = 0.1 config constant, TAU_E = 1000)
    float pos = pos_estimate[0];
    float pe  = pos + (period_bound(center - pos) / 1000.0f + angular_velocity[0]) * 0.1f;
    pos = period_bound(pe);

    float dd = period_bound(xn - pos) / GW;
    const float motion = 3.0f * expf(-0.25f * dd * dd);

    // recurrent input: circular convolution
    float irec = 0.0f;
    #pragma unroll 8
    for (int m = 0; m < N_NEUR; m++)
        irec = fmaf(s_cn[m], s_rr[(n - m) & (N_NEUR - 1)], irec);

    const float ib = bear / sum_hpc;
    const float input_total = motion + irec + ib * sen2hd[0];

    // exact exponential ODE step for u (v1 never feeds the output)
    const float dt_ode = shared_t[1] - shared_t[0];
    const float C1 = input_total - v[n];
    const float u1 = C1 + (u[n] - C1) * expf(-dt_ode /* / TAU=1 */);

    const float un = u1 > 0.0f ? u1 : 0.0f;
    const float r1 = un * un;

    s_red[n] = r1;
    __syncthreads();
    #pragma unroll
    for (int off = 256; off > 0; off >>= 1) {
        if (n < off) s_red[n] += s_red[n + off];
        __syncthreads();
    }
    const float sum_r1 = s_red[0];

    out[n] = r1 / (1.0f + KPAR * sum_r1);

    // reset for next graph replay (all threads are past their g_sum_hpc read:
    // the block-wide reductions above synchronized the block)
    if (n == 0) { g_count = 0; g_ticket = 0; g_sum_hpc = 0.0f; }
}

// ---------------------------------------------------------------------------
// Launch
// ---------------------------------------------------------------------------
extern "C" void kernel_launch(void* const* d_in, const int* in_sizes, int n_in,
                              void* d_out, int out_size) {
    const float* conn      = (const float*)d_in[0];   // (P, 512, 30)
    const float* r         = (const float*)d_in[1];   // (512,)
    const float* u         = (const float*)d_in[2];   // (512,)
    const float* v         = (const float*)d_in[3];   // (512,)
    const float* r_hpc     = (const float*)d_in[4];   // (P,)
    const float* r_bearing = (const float*)d_in[5];   // (30,)
    const float* pos_est   = (const float*)d_in[6];   // (1,)
    const float* ang_vel   = (const float*)d_in[7];   // (1,)
    // d_in[8] = HD, unused (get_HD = 0 path)
    const float* sen2hd    = (const float*)d_in[9];   // (1,)
    const float* shared_t  = (const float*)d_in[10];  // (2,)
    float* out = (float*)d_out;

    const int P = in_sizes[4];  // r_hpc length

    const int smem_bytes = DEPTH * SLAB_BYTES;  // 184320 per block
    cudaFuncSetAttribute(fused_kernel,
                         cudaFuncAttributeMaxDynamicSharedMemorySize, smem_bytes);

    fused_kernel<<<GRID, N_NEUR, smem_bytes>>>(
        conn, r, u, v, r_hpc, r_bearing, pos_est, ang_vel, sen2hd, shared_t,
        out, P);
}

// round 17
// speedup vs baseline: 1.0175x; 1.0175x over previous
#include <cuda_runtime.h>
#include <math.h>
#include <stdint.h>

#define PI_F      3.14159265358979323846f
#define TWO_PI_F  6.28318530717958647692f
#define N_NEUR    512
#define GW        (PI_F / 4.0f)
#define GRID      148
#define DEPTH     3
#define NL        30
#define TG        8                        // slabs per stolen ticket
#define SLAB_FLOATS (N_NEUR * NL)          // 15360 floats
#define SLAB_BYTES  (SLAB_FLOATS * 4)      // 61440 bytes
#define HALF_FLOATS (SLAB_FLOATS / 2)      // 7680 floats (rows 0-255 / 256-511)
#define HALF_BYTES  (HALF_FLOATS * 4)      // 30720 bytes

// Scratch (static device memory, zero-initialized; no allocations anywhere)
__device__ float g_bearing[N_NEUR];        // accumulated across blocks
__device__ float g_sum_hpc = 0.0f;
__device__ int   g_count  = 0;
__device__ int   g_ticket = 0;

__device__ __forceinline__ float period_bound(float d) {
    float m = fmodf(d + PI_F, TWO_PI_F);
    if (m < 0.0f) m += TWO_PI_F;
    return m - PI_F;
}

__device__ __forceinline__ uint32_t smem_u32(const void* p) {
    return (uint32_t)__cvta_generic_to_shared(p);
}
__device__ __forceinline__ void mbar_init(uint32_t mb, uint32_t count) {
    asm volatile("mbarrier.init.shared.b64 [%0], %1;" :: "r"(mb), "r"(count) : "memory");
}
// Proven 1:1 protocol: one expect_tx + one bulk copy per mbarrier.
__device__ __forceinline__ void bulk_load(uint32_t dst_smem, const void* src_gmem,
                                          uint32_t bytes, uint32_t mb) {
    asm volatile("mbarrier.arrive.expect_tx.shared.b64 _, [%0], %1;"
                 :: "r"(mb), "r"(bytes) : "memory");
    asm volatile("cp.async.bulk.shared::cluster.global.mbarrier::complete_tx::bytes "
                 "[%0], [%1], %2, [%3];"
                 :: "r"(dst_smem), "l"(src_gmem), "r"(bytes), "r"(mb) : "memory");
}
__device__ __forceinline__ void mbar_wait(uint32_t mb, uint32_t parity) {
    asm volatile(
        "{\n\t"
        ".reg .pred p;\n\t"
        "WL_%=:\n\t"
        "mbarrier.try_wait.parity.shared.b64 p, [%0], %1;\n\t"
        "@!p bra WL_%=;\n\t"
        "}"
        :: "r"(mb), "r"(parity) : "memory");
}

// ---------------------------------------------------------------------------
// Fused persistent kernel (R15 proven core + per-half sub-slot barriers).
//  148 blocks x 512 threads, dynamic work stealing (TG=8 slabs/ticket),
//  DEPTH=3 ring gated by __syncthreads. Each slot is filled as TWO 30720B
//  cp.async.bulk copies, each with its OWN mbarrier (1:1 expect_tx/copy, the
//  protocol every passing kernel used). Consumer thread tid waits only on
//  the sub-slot holding its row (tid>>8) -> 6 outstanding TMA ops and
//  earlier compute start for the lower half. Refill still gated by the
//  block-wide __syncthreads, thread 0 refills both halves.
//  Thread n accumulates sum_p w_p * dot(conn[p,n,:], rb) and publishes via
//  one coalesced atomicAdd into g_bearing[n]; thread 0 streams the block's
//  share of sum(r_hpc). Last block runs the small ODE / convolution stage
//  and resets globals for the next graph replay.
// ---------------------------------------------------------------------------
__global__ void __launch_bounds__(N_NEUR, 1) fused_kernel(
    const float* __restrict__ conn,      // (P, 512, 30)
    const float* __restrict__ r,
    const float* __restrict__ u,
    const float* __restrict__ v,
    const float* __restrict__ r_hpc,     // (P,)
    const float* __restrict__ r_bearing, // (30,)
    const float* __restrict__ pos_estimate,
    const float* __restrict__ angular_velocity,
    const float* __restrict__ sen2hd,
    const float* __restrict__ shared_t,
    float* __restrict__ out,
    int P)
{
    extern __shared__ float buf[];                 // DEPTH * SLAB_FLOATS
    __shared__ __align__(8) unsigned long long mbar[DEPTH][2];
    __shared__ int   s_pidx[DEPTH];
    __shared__ int   s_last;
    __shared__ float s_red[N_NEUR];
    __shared__ float s_rr[N_NEUR];
    __shared__ float s_cn[N_NEUR];

    const int tid  = threadIdx.x;
    const int half = tid >> 8;            // 0: rows 0-255, 1: rows 256-511

    // rb into registers (uniform; compile-time indices)
    float rbv[NL];
    #pragma unroll
    for (int l = 0; l < NL; l++) rbv[l] = __ldg(r_bearing + l);

    // ticket state lives in thread 0's registers
    int cur = 0, rem = 0;

    if (tid == 0) {
        #pragma unroll
        for (int s = 0; s < DEPTH; s++) {
            mbar_init(smem_u32(&mbar[s][0]), 1u);
            mbar_init(smem_u32(&mbar[s][1]), 1u);
        }
        // preload up to DEPTH slabs (two half-copies each)
        for (int s = 0; s < DEPTH; s++) {
            if (rem == 0) {
                cur = atomicAdd(&g_ticket, TG);
                rem = (cur < P) ? min(TG, P - cur) : 0;
            }
            if (rem > 0) {
                s_pidx[s] = cur;
                const float* src = conn + (size_t)cur * SLAB_FLOATS;
                bulk_load(smem_u32(buf + s * SLAB_FLOATS),
                          src, HALF_BYTES, smem_u32(&mbar[s][0]));
                bulk_load(smem_u32(buf + s * SLAB_FLOATS + HALF_FLOATS),
                          src + HALF_FLOATS, HALF_BYTES, smem_u32(&mbar[s][1]));
                cur++; rem--;
            } else {
                s_pidx[s] = -1;
            }
        }
    }
    __syncthreads();  // barriers + preload indices visible

    float acc  = 0.0f;
    float wsum = 0.0f;                    // thread 0 only: block's sum(r_hpc)
    for (int it = 0; ; it++) {
        const int s = it % DEPTH;
        const int p = s_pidx[s];          // written >= DEPTH-1 barriers ago
        if (p < 0) break;

        const float w = __ldg(r_hpc + p); // broadcast load, issues early
        if (tid == 0) wsum += w;          // p's are disjoint across blocks
        // wait only on the sub-slot holding this thread's row
        mbar_wait(smem_u32(&mbar[s][half]), (uint32_t)((it / DEPTH) & 1));

        const float2* row = (const float2*)(buf + s * SLAB_FLOATS) + tid * (NL / 2);
        float dot = 0.0f;
        #pragma unroll
        for (int l = 0; l < NL / 2; l++) {
            float2 v2 = row[l];
            dot = fmaf(v2.x, rbv[2 * l],     dot);
            dot = fmaf(v2.y, rbv[2 * l + 1], dot);
        }
        acc = fmaf(w, dot, acc);

        __syncthreads();                  // everyone done with buf[s]
        if (tid == 0) {
            if (rem == 0) {
                cur = atomicAdd(&g_ticket, TG);
                rem = (cur < P) ? min(TG, P - cur) : 0;
            }
            if (rem > 0) {
                s_pidx[s] = cur;
                const float* src = conn + (size_t)cur * SLAB_FLOATS;
                bulk_load(smem_u32(buf + s * SLAB_FLOATS),
                          src, HALF_BYTES, smem_u32(&mbar[s][0]));
                bulk_load(smem_u32(buf + s * SLAB_FLOATS + HALF_FLOATS),
                          src + HALF_FLOATS, HALF_BYTES, smem_u32(&mbar[s][1]));
                cur++; rem--;
            } else {
                s_pidx[s] = -1;
            }
        }
    }

    // publish: coalesced float atomics, overlapped with others' streaming
    atomicAdd(&g_bearing[tid], acc);
    if (tid == 0) atomicAdd(&g_sum_hpc, wsum);
    __threadfence();
    __syncthreads();
    if (tid == 0) {
        int old = atomicAdd(&g_count, 1);
        s_last = (old == GRID - 1);
    }
    __syncthreads();
    if (!s_last) return;

    // ------------------- last block: small final stage -------------------
    __threadfence();  // acquire all blocks' contributions

    const int n = tid;

    const float bear    = g_bearing[n];   // all adds ordered before counter
    const float sum_hpc = g_sum_hpc;
    g_bearing[n] = 0.0f;                  // reset for next graph replay
                                          // (only this block is alive now)

    const float DX   = TWO_PI_F / 512.0f;
    const float J0   = 20.0f / 512.0f;
    const float KPAR = 0.8f / 512.0f * 20.0f;

    const float xn = -PI_F + n * DX;
    const float rn = r[n];
    s_rr[n] = rn;
    {
        float dj = period_bound(n * DX);
        float q  = dj / GW;
        s_cn[n] = J0 * expf(-0.5f * q * q) / (TWO_PI_F * GW * GW);
    }

    // bump center: angle(sum exp(i x) r)
    s_red[n] = cosf(xn) * rn;
    __syncthreads();
    #pragma unroll
    for (int off = 256; off > 0; off >>= 1) {
        if (n < off) s_red[n] += s_red[n + off];
        __syncthreads();
    }
    const float csum = s_red[0];
    __syncthreads();
    s_red[n] = sinf(xn) * rn;
    __syncthreads();
    #pragma unroll
    for (int off = 256; off > 0; off >>= 1) {
        if (n < off) s_red[n] += s_red[n + off];
        __syncthreads();
    }
    const float ssum = s_red[0];
    __syncthreads();
    const float center = atan2f(ssum, csum);

    // path integration (DT = 0.1 config constant, TAU_E = 1000)
    float pos = pos_estimate[0];
    float pe  = pos + (period_bound(center - pos) / 1000.0f + angular_velocity[0]) * 0.1f;
    pos = period_bound(pe);

    float dd = period_bound(xn - pos) / GW;
    const float motion = 3.0f * expf(-0.25f * dd * dd);

    // recurrent input: circular convolution
    float irec = 0.0f;
    #pragma unroll 8
    for (int m = 0; m < N_NEUR; m++)
        irec = fmaf(s_cn[m], s_rr[(n - m) & (N_NEUR - 1)], irec);

    const float ib = bear / sum_hpc;
    const float input_total = motion + irec + ib * sen2hd[0];

    // exact exponential ODE step for u (v1 never feeds the output)
    const float dt_ode = shared_t[1] - shared_t[0];
    const float C1 = input_total - v[n];
    const float u1 = C1 + (u[n] - C1) * expf(-dt_ode /* / TAU=1 */);

    const float un = u1 > 0.0f ? u1 : 0.0f;
    const float r1 = un * un;

    s_red[n] = r1;
    __syncthreads();
    #pragma unroll
    for (int off = 256; off > 0; off >>= 1) {
        if (n < off) s_red[n] += s_red[n + off];
        __syncthreads();
    }
    const float sum_r1 = s_red[0];

    out[n] = r1 / (1.0f + KPAR * sum_r1);

    // reset for next graph replay (all threads are past their g_sum_hpc read:
    // the block-wide reductions above synchronized the block)
    if (n == 0) { g_count = 0; g_ticket = 0; g_sum_hpc = 0.0f; }
}

// ---------------------------------------------------------------------------
// Launch
// ---------------------------------------------------------------------------
extern "C" void kernel_launch(void* const* d_in, const int* in_sizes, int n_in,
                              void* d_out, int out_size) {
    const float* conn      = (const float*)d_in[0];   // (P, 512, 30)
    const float* r         = (const float*)d_in[1];   // (512,)
    const float* u         = (const float*)d_in[2];   // (512,)
    const float* v         = (const float*)d_in[3];   // (512,)
    const float* r_hpc     = (const float*)d_in[4];   // (P,)
    const float* r_bearing = (const float*)d_in[5];   // (30,)
    const float* pos_est   = (const float*)d_in[6];   // (1,)
    const float* ang_vel   = (const float*)d_in[7];   // (1,)
    // d_in[8] = HD, unused (get_HD = 0 path)
    const float* sen2hd    = (const float*)d_in[9];   // (1,)
    const float* shared_t  = (const float*)d_in[10];  // (2,)
    float* out = (float*)d_out;

    const int P = in_sizes[4];  // r_hpc length

    const int smem_bytes = DEPTH * SLAB_BYTES;  // 184320 per block
    cudaFuncSetAttribute(fused_kernel,
                         cudaFuncAttributeMaxDynamicSharedMemorySize, smem_bytes);

    fused_kernel<<<GRID, N_NEUR, smem_bytes>>>(
        conn, r, u, v, r_hpc, r_bearing, pos_est, ang_vel, sen2hd, shared_t,
        out, P);
}